// round 10
// baseline (speedup 1.0000x reference)
#include <cuda_runtime.h>
#include <cuda_bf16.h>
#include <cstdint>

#define N_MAX 50000
#define E_MAX 400000
#define DIM 128

__device__ __align__(16) float g_h[N_MAX * DIM];
__device__ __align__(16) float g_agg[N_MAX * DIM];
__device__ int   g_is64;
// CSR scratch
__device__ int g_cnt[N_MAX];
__device__ int g_row[N_MAX + 1];
__device__ int g_cur[N_MAX];
__device__ int g_src[E_MAX];
// pre-split tf32 weights: [0]=W1, [1]=W2
__device__ __align__(16) float g_Wh[2][DIM * DIM];
__device__ __align__(16) float g_Wl[2][DIM * DIM];

// ---------------------------------------------------------------------------
__device__ __forceinline__ uint32_t f2tf32(float x)
{
    uint32_t r;
    asm("cvt.rna.tf32.f32 %0, %1;" : "=r"(r) : "f"(x));
    return r;
}

__device__ __forceinline__ void mma8(float* d,
    uint32_t a0, uint32_t a1, uint32_t a2, uint32_t a3,
    uint32_t b0, uint32_t b1)
{
    asm volatile(
        "mma.sync.aligned.m16n8k8.row.col.f32.tf32.tf32.f32 "
        "{%0,%1,%2,%3}, {%4,%5,%6,%7}, {%8,%9}, {%0,%1,%2,%3};"
        : "+f"(d[0]), "+f"(d[1]), "+f"(d[2]), "+f"(d[3])
        : "r"(a0), "r"(a1), "r"(a2), "r"(a3), "r"(b0), "r"(b1));
}

// ---------------------------------------------------------------------------
// Edge-index dtype probe (int64 data has all odd 32-bit words == 0).
// ---------------------------------------------------------------------------
__global__ void detect_kernel(const int* __restrict__ ei_words)
{
    if (threadIdx.x == 0) {
        int all_zero = 1;
        for (int i = 0; i < 128; i++)
            if (ei_words[2 * i + 1] != 0) { all_zero = 0; break; }
        g_is64 = all_zero;
    }
}

__global__ void zero_cnt_kernel(int N)
{
    int i = blockIdx.x * blockDim.x + threadIdx.x;
    if (i < N) g_cnt[i] = 0;
}

// ---------------------------------------------------------------------------
// One-shot Markidis split of both weight matrices into g_Wh / g_Wl.
// ---------------------------------------------------------------------------
__global__ void split_kernel(const float* __restrict__ W1,
                             const float* __restrict__ W2)
{
    int i = blockIdx.x * blockDim.x + threadIdx.x;   // 0 .. 32767
    int w = i >> 14;
    int j = i & 16383;
    float v = w ? __ldg(W2 + j) : __ldg(W1 + j);
    uint32_t hi = f2tf32(v);
    g_Wh[w][j] = __uint_as_float(hi);
    g_Wl[w][j] = __uint_as_float(f2tf32(v - __uint_as_float(hi)));
}

// ---------------------------------------------------------------------------
// CSR build: histogram of dst, exclusive scan, then cursor-scatter of src.
// ---------------------------------------------------------------------------
__device__ __forceinline__ int load_idx(const void* ei_raw, long long pos)
{
    if (g_is64) return (int)((const long long*)ei_raw)[pos];
    return ((const int*)ei_raw)[pos];
}

__global__ void __launch_bounds__(256)
count_kernel(const void* __restrict__ ei_raw, int nE)
{
    int e = blockIdx.x * blockDim.x + threadIdx.x;
    if (e >= nE) return;
    int dst = load_idx(ei_raw, (long long)nE + e);
    atomicAdd(&g_cnt[dst], 1);
}

__global__ void __launch_bounds__(1024)
scan_kernel(int N)
{
    __shared__ int wsum[32];
    __shared__ int total_sh;
    const int t = threadIdx.x;
    const int lane = t & 31, warp = t >> 5;
    const int chunk = (N + 1023) >> 10;
    const int lo = t * chunk;
    const int hi = min(lo + chunk, N);

    int sum = 0;
    for (int i = lo; i < hi; i++) sum += g_cnt[i];

    // inclusive warp scan of per-thread sums
    int v = sum;
#pragma unroll
    for (int d = 1; d < 32; d <<= 1) {
        int u = __shfl_up_sync(~0u, v, d);
        if (lane >= d) v += u;
    }
    if (lane == 31) wsum[warp] = v;
    __syncthreads();
    if (warp == 0) {
        int w = wsum[lane];
#pragma unroll
        for (int d = 1; d < 32; d <<= 1) {
            int u = __shfl_up_sync(~0u, w, d);
            if (lane >= d) w += u;
        }
        wsum[lane] = w;                    // inclusive warp totals
        if (lane == 31) total_sh = w;
    }
    __syncthreads();

    int warp_off = (warp > 0) ? wsum[warp - 1] : 0;
    int off = warp_off + v - sum;          // exclusive prefix for this thread
    for (int i = lo; i < hi; i++) {
        int c = g_cnt[i];
        g_row[i] = off;
        g_cur[i] = off;
        off += c;
    }
    if (t == 0) g_row[N] = total_sh;
}

__global__ void __launch_bounds__(256)
scatter_kernel(const void* __restrict__ ei_raw, int nE)
{
    int e = blockIdx.x * blockDim.x + threadIdx.x;
    if (e >= nE) return;
    int src = load_idx(ei_raw, e);
    int dst = load_idx(ei_raw, (long long)nE + e);
    int pos = atomicAdd(&g_cur[dst], 1);
    g_src[pos] = src;
}

// ---------------------------------------------------------------------------
// Aggregation: one warp per node, lane = one float4 of the row.
// Sequential register accumulation over the node's sorted edge list (no
// atomics), unroll-4 for MLP, normalized by exact degree, streaming write.
// ---------------------------------------------------------------------------
__global__ void __launch_bounds__(256)
agg_kernel(int N)
{
    int wid  = (blockIdx.x * blockDim.x + threadIdx.x) >> 5;
    int lane = threadIdx.x & 31;
    if (wid >= N) return;

    const int e0 = g_row[wid], e1 = g_row[wid + 1];
    float4 acc = make_float4(0.f, 0.f, 0.f, 0.f);

    int e = e0;
    for (; e + 4 <= e1; e += 4) {
        int s0 = g_src[e], s1 = g_src[e + 1], s2 = g_src[e + 2], s3 = g_src[e + 3];
        float4 v0 = __ldg((const float4*)(g_h + (size_t)s0 * DIM) + lane);
        float4 v1 = __ldg((const float4*)(g_h + (size_t)s1 * DIM) + lane);
        float4 v2 = __ldg((const float4*)(g_h + (size_t)s2 * DIM) + lane);
        float4 v3 = __ldg((const float4*)(g_h + (size_t)s3 * DIM) + lane);
        acc.x += v0.x + v1.x + v2.x + v3.x;
        acc.y += v0.y + v1.y + v2.y + v3.y;
        acc.z += v0.z + v1.z + v2.z + v3.z;
        acc.w += v0.w + v1.w + v2.w + v3.w;
    }
    for (; e < e1; e++) {
        int s = g_src[e];
        float4 v = __ldg((const float4*)(g_h + (size_t)s * DIM) + lane);
        acc.x += v.x; acc.y += v.y; acc.z += v.z; acc.w += v.w;
    }

    const float inv = 1.f / fmaxf((float)(e1 - e0), 1.f);
    acc.x *= inv; acc.y *= inv; acc.z *= inv; acc.w *= inv;
    ((float4*)(g_agg + (size_t)wid * DIM))[lane] = acc;
}

// ---------------------------------------------------------------------------
// tf32 tensor-core GEMM, 3-term Markidis (~fp32 accuracy):
//   OUT[N,128] = act( IN[N,128] @ W[128,128]^T + b )
// MODE 0: IN = X, relu.  MODE 1: IN = g_agg + g_h (agg pre-normalized).
// BM=64, BN=128, BK=16, 256 thr (8 warps: 4 along M x 2 along N).
// Register-prefetch pipeline; smem stride 20 -> conflict-free fragment LDS.
// ---------------------------------------------------------------------------
template <int MODE, int WIDX>
__global__ void __launch_bounds__(256, 3)
gemm_tc(const float* __restrict__ X, const float* __restrict__ bias,
        float* __restrict__ OUT, int N)
{
    constexpr int LDSH = 20;
    __shared__ float Ahi[64 * LDSH], Alo[64 * LDSH];
    __shared__ float Whi[128 * LDSH], Wlo[128 * LDSH];

    const int t    = threadIdx.x;
    const int lane = t & 31;
    const int warp = t >> 5;
    const int g    = lane >> 2;
    const int tig  = lane & 3;
    const int wm   = warp & 3;
    const int wn   = warp >> 2;
    const int row0 = blockIdx.x * 64;

    float acc[8][4];
#pragma unroll
    for (int nt = 0; nt < 8; nt++)
#pragma unroll
        for (int c = 0; c < 4; c++) acc[nt][c] = 0.f;

    const int fr = t >> 2;
    const int fs = (t & 3) * 4;
    const int gr = row0 + fr;
    const int wr0 = t >> 2, ws0 = (t & 3) * 4;
    const int wr1 = wr0 + 64, ws1 = ws0;

    float4 a_p0 = make_float4(0.f, 0.f, 0.f, 0.f), a_p1 = a_p0;
    float4 w_h0, w_l0, w_h1, w_l1;

    auto prefetch = [&](int k0) {
        if (gr < N) {
            if (MODE == 0) {
                a_p0 = __ldg((const float4*)(X + (size_t)gr * DIM + k0 + fs));
            } else {
                a_p0 = *(const float4*)(g_agg + (size_t)gr * DIM + k0 + fs);
                a_p1 = *(const float4*)(g_h   + (size_t)gr * DIM + k0 + fs);
            }
        } else {
            a_p0 = make_float4(0.f, 0.f, 0.f, 0.f);
            a_p1 = a_p0;
        }
        w_h0 = *(const float4*)(&g_Wh[WIDX][wr0 * DIM + k0 + ws0]);
        w_l0 = *(const float4*)(&g_Wl[WIDX][wr0 * DIM + k0 + ws0]);
        w_h1 = *(const float4*)(&g_Wh[WIDX][wr1 * DIM + k0 + ws1]);
        w_l1 = *(const float4*)(&g_Wl[WIDX][wr1 * DIM + k0 + ws1]);
    };

    prefetch(0);

    for (int k0 = 0; k0 < DIM; k0 += 16) {
        float v[4];
        if (MODE == 0) {
            v[0] = a_p0.x; v[1] = a_p0.y; v[2] = a_p0.z; v[3] = a_p0.w;
        } else {
            v[0] = a_p0.x + a_p1.x; v[1] = a_p0.y + a_p1.y;
            v[2] = a_p0.z + a_p1.z; v[3] = a_p0.w + a_p1.w;
        }
        float4 ah4, al4;
        {
            uint32_t h0 = f2tf32(v[0]), h1 = f2tf32(v[1]),
                     h2 = f2tf32(v[2]), h3 = f2tf32(v[3]);
            ah4 = make_float4(__uint_as_float(h0), __uint_as_float(h1),
                              __uint_as_float(h2), __uint_as_float(h3));
            al4 = make_float4(
                __uint_as_float(f2tf32(v[0] - __uint_as_float(h0))),
                __uint_as_float(f2tf32(v[1] - __uint_as_float(h1))),
                __uint_as_float(f2tf32(v[2] - __uint_as_float(h2))),
                __uint_as_float(f2tf32(v[3] - __uint_as_float(h3))));
        }
        *(float4*)&Ahi[fr * LDSH + fs] = ah4;
        *(float4*)&Alo[fr * LDSH + fs] = al4;
        *(float4*)&Whi[wr0 * LDSH + ws0] = w_h0;
        *(float4*)&Wlo[wr0 * LDSH + ws0] = w_l0;
        *(float4*)&Whi[wr1 * LDSH + ws1] = w_h1;
        *(float4*)&Wlo[wr1 * LDSH + ws1] = w_l1;
        __syncthreads();

        if (k0 + 16 < DIM) prefetch(k0 + 16);

#pragma unroll
        for (int kk = 0; kk < 16; kk += 8) {
            const int r_ = wm * 16 + g;
            const int c0 = kk + tig, c1 = kk + tig + 4;
            uint32_t ah0 = __float_as_uint(Ahi[r_ * LDSH + c0]);
            uint32_t ah1 = __float_as_uint(Ahi[(r_ + 8) * LDSH + c0]);
            uint32_t ah2 = __float_as_uint(Ahi[r_ * LDSH + c1]);
            uint32_t ah3 = __float_as_uint(Ahi[(r_ + 8) * LDSH + c1]);
            uint32_t al0 = __float_as_uint(Alo[r_ * LDSH + c0]);
            uint32_t al1 = __float_as_uint(Alo[(r_ + 8) * LDSH + c0]);
            uint32_t al2 = __float_as_uint(Alo[r_ * LDSH + c1]);
            uint32_t al3 = __float_as_uint(Alo[(r_ + 8) * LDSH + c1]);
#pragma unroll
            for (int nt = 0; nt < 8; nt++) {
                const int n_ = wn * 64 + nt * 8 + g;
                uint32_t bh0 = __float_as_uint(Whi[n_ * LDSH + c0]);
                uint32_t bh1 = __float_as_uint(Whi[n_ * LDSH + c1]);
                uint32_t bl0 = __float_as_uint(Wlo[n_ * LDSH + c0]);
                uint32_t bl1 = __float_as_uint(Wlo[n_ * LDSH + c1]);
                mma8(acc[nt], ah0, ah1, ah2, ah3, bh0, bh1);
                mma8(acc[nt], ah0, ah1, ah2, ah3, bl0, bl1);
                mma8(acc[nt], al0, al1, al2, al3, bh0, bh1);
            }
        }
        __syncthreads();
    }

#pragma unroll
    for (int nt = 0; nt < 8; nt++) {
        int c = wn * 64 + nt * 8 + 2 * tig;
        float b0 = __ldg(bias + c), b1 = __ldg(bias + c + 1);
        int r_ = row0 + wm * 16 + g;
        if (r_ < N) {
            float o0 = acc[nt][0] + b0, o1 = acc[nt][1] + b1;
            if (MODE == 0) { o0 = fmaxf(o0, 0.f); o1 = fmaxf(o1, 0.f); }
            *(float2*)(OUT + (size_t)r_ * DIM + c) = make_float2(o0, o1);
        }
        int r2 = r_ + 8;
        if (r2 < N) {
            float o2 = acc[nt][2] + b0, o3 = acc[nt][3] + b1;
            if (MODE == 0) { o2 = fmaxf(o2, 0.f); o3 = fmaxf(o3, 0.f); }
            *(float2*)(OUT + (size_t)r2 * DIM + c) = make_float2(o2, o3);
        }
    }
}

// ---------------------------------------------------------------------------
extern "C" void kernel_launch(void* const* d_in, const int* in_sizes, int n_in,
                              void* d_out, int out_size)
{
    const float* x  = (const float*)d_in[0];
    const void*  ei = d_in[1];
    const float* W1 = (const float*)d_in[2];
    const float* b1 = (const float*)d_in[3];
    const float* W2 = (const float*)d_in[4];
    const float* b2 = (const float*)d_in[5];
    float*       out = (float*)d_out;

    const int N  = in_sizes[0] / DIM;      // 50000
    const int nE = in_sizes[1] / 2;        // 400000

    float* h_ptr;
    cudaGetSymbolAddress((void**)&h_ptr, g_h);

    const int gemm_blocks = (N + 63) / 64;
    const int eb = (nE + 255) / 256;

    // 0) setup: dtype probe, histogram zero, weight split
    detect_kernel<<<1, 32>>>((const int*)ei);
    zero_cnt_kernel<<<(N + 255) / 256, 256>>>(N);
    split_kernel<<<128, 256>>>(W1, W2);

    // 1) CSR build
    count_kernel<<<eb, 256>>>(ei, nE);
    scan_kernel<<<1, 1024>>>(N);
    scatter_kernel<<<eb, 256>>>(ei, nE);

    // 2) h = relu(x @ W1^T + b1)
    gemm_tc<0, 0><<<gemm_blocks, 256>>>(x, b1, h_ptr, N);

    // 3) agg[n] = mean over edges of h[src]  (no atomics)
    agg_kernel<<<(N * 32 + 255) / 256, 256>>>(N);

    // 4) out = (agg + h) @ W2^T + b2
    gemm_tc<1, 1><<<gemm_blocks, 256>>>(nullptr, b2, out, N);
}